// round 9
// baseline (speedup 1.0000x reference)
#include <cuda_runtime.h>
#include <cstdint>

#define B_    16
#define CIN_  64
#define COUT_ 64
#define HH    256
#define WW    256
#define HW    (HH * WW)
#define EPSF  1e-8f

// Demodulated tf32 weights in fragment-consumption order:
// [b][half 0..1][tap 0..8][kk 0..3][coh 0..1][ntp 0..1][lane 0..31][4 words]
__device__ __align__(16) float g_wt[B_ * 2 * 9 * 4 * 2 * 2 * 32 * 4];

__device__ __forceinline__ float f2tf32f(float x) {
    uint32_t r;
    asm("cvt.rna.tf32.f32 %0, %1;" : "=r"(r) : "f"(x));
    return __uint_as_float(r);
}

#define MMA_OP(d, a, b0, b1)                                                  \
    asm volatile(                                                             \
        "mma.sync.aligned.m16n8k8.row.col.f32.tf32.tf32.f32 "                 \
        "{%0,%1,%2,%3},{%4,%5,%6,%7},{%8,%9},{%0,%1,%2,%3};"                  \
        : "+f"((d)[0]), "+f"((d)[1]), "+f"((d)[2]), "+f"((d)[3])              \
        : "r"((a)[0]), "r"((a)[1]), "r"((a)[2]), "r"((a)[3]),                 \
          "r"(b0), "r"(b1))

// ---------------------------------------------------------------------------
// Kernel 1: modulate + demodulate + tf32-round + swizzle into fragment order
// grid (COUT, B), block CIN.
// ---------------------------------------------------------------------------
__global__ void modw_kernel(const float* __restrict__ w,
                            const float* __restrict__ y,
                            float* __restrict__ wt) {
    const int co = blockIdx.x;
    const int b  = blockIdx.y;
    const int ci = threadIdx.x;

    const float c  = 1.0f / 24.0f;               // (64*9)^-0.5
    const float yv = y[b * CIN_ + ci] * c;

    float v[9];
    float s = 0.0f;
    const float* wp = w + (co * CIN_ + ci) * 9;
#pragma unroll
    for (int t = 0; t < 9; t++) {
        v[t] = wp[t] * yv;
        s += v[t] * v[t];
    }
#pragma unroll
    for (int off = 16; off > 0; off >>= 1)
        s += __shfl_down_sync(0xffffffffu, s, off);
    __shared__ float ps[2];
    if ((ci & 31) == 0) ps[ci >> 5] = s;
    __syncthreads();
    const float d = rsqrtf(ps[0] + ps[1] + EPSF);

    const int half = ci >> 5;
    const int kk   = (ci >> 3) & 3;
    const int k    = ci & 7;
    const int p    = k & 3;
    const int sgm  = k >> 2;
    const int coh  = co >> 5;
    const int cot  = (co >> 3) & 3;
    const int ntp  = cot >> 1;
    const int nto  = cot & 1;
    const int lane = (co & 7) * 4 + p;
    const int word = nto * 2 + sgm;

#pragma unroll
    for (int t = 0; t < 9; t++) {
        const size_t idx =
            ((((((size_t)((b * 2 + half) * 9 + t) * 4 + kk) * 2 + coh) * 2 + ntp)
              * 32 + lane) * 4) + word;
        wt[idx] = f2tf32f(v[t] * d);
    }
}

// ---------------------------------------------------------------------------
// Kernel 2: tf32 mma.sync implicit-GEMM conv, M32 x N32 warp tile.
// CIN split into 2 halves of 32 staged sequentially (smem 33.8KB, 4 CTAs/SM).
// B operand loaded straight from gmem (fragment order, L1-resident LDG.128).
// No barriers inside the tap loop. Division-free staging loop.
// CTA: 128 px (2h x 64w) x 64 co, 8 warps: (wid&3)->px group, (wid>>2)->co half.
// xs[32 ci][4 r][66 w], plane stride 264 (conflict-free A LDS).
// ---------------------------------------------------------------------------
#define XS_WORDS (32 * 264)        // 33.8 KB
#define DYN_SMEM (XS_WORDS * 4)

__global__ void __launch_bounds__(256, 4)
conv_mma_kernel(const float* __restrict__ X,
                const float* __restrict__ wt,
                float* __restrict__ out) {
    extern __shared__ __align__(16) float smem[];
    float* xs = smem;

    const int tid  = threadIdx.x;
    const int lane = tid & 31;
    const int wid  = tid >> 5;
    const int coh  = wid >> 2;           // co half (0/1)
    const int px0  = (wid & 3) * 32;     // warp pixel base

    const int b  = blockIdx.z;
    const int h0 = blockIdx.y * 2;
    const int w0 = blockIdx.x * 64;

    const float* Xb = X + (size_t)b * CIN_ * HW;
    // B fragment base for this warp: + coh block + lane (uint4 granularity)
    const uint4* WbF = (const uint4*)(wt + (size_t)b * 36864) + coh * 64 + lane;

    // staging start coordinates (one div at entry, incremental after)
    const int c_init   = tid % 66;
    const int row_init = tid / 66;       // row = ci*4 + r

    float acc[2][4][4];
#pragma unroll
    for (int mt = 0; mt < 2; mt++)
#pragma unroll
        for (int nt = 0; nt < 4; nt++)
#pragma unroll
            for (int q = 0; q < 4; q++) acc[mt][nt][q] = 0.0f;

#pragma unroll
    for (int half = 0; half < 2; half++) {
        // ---- stage X half-tile (32 ci planes), tf32-rounded, div-free ----
        if (half == 1) __syncthreads();  // all warps done consuming half 0
        {
            const float* Xh = Xb + (size_t)(half * 32) * HW;
            int c = c_init, row = row_init, idx = tid;
#pragma unroll
            for (int j = 0; j < 33; j++) {
                const int gh = h0 - 1 + (row & 3);
                const int gw = w0 - 1 + c;
                float v = 0.0f;
                if ((unsigned)gh < (unsigned)HH && (unsigned)gw < (unsigned)WW)
                    v = Xh[(size_t)(row >> 2) * HW + gh * WW + gw];
                xs[idx] = f2tf32f(v);
                // advance by 256 elements: 256 = 3*66 + 58
                idx += 256;
                c += 58; row += 3;
                if (c >= 66) { c -= 66; row += 1; }
            }
        }
        __syncthreads();

#pragma unroll
        for (int t = 0; t < 9; t++) {
            const int kh = t / 3, kw = t - kh * 3;
            const float* abase = xs + (size_t)(lane & 3) * 264
                               + ((px0 >> 6) + kh) * 66
                               + (px0 & 63) + (lane >> 2) + kw;
            // fragment stride per kk = 512 words = 128 uint4
            const uint4* bp = WbF + (size_t)((half * 9 + t) * 4) * 128;

#pragma unroll
            for (int kk = 0; kk < 4; kk++) {
                const uint4 b0 = __ldg(bp + kk * 128);        // co tiles 0,1
                const uint4 b1 = __ldg(bp + kk * 128 + 32);   // co tiles 2,3

                const float* ap = abase + kk * (8 * 264);
                uint32_t a0[4], a1[4];
                a0[0] = __float_as_uint(ap[0]);
                a0[1] = __float_as_uint(ap[8]);
                a0[2] = __float_as_uint(ap[1056]);
                a0[3] = __float_as_uint(ap[1064]);
                a1[0] = __float_as_uint(ap[16]);
                a1[1] = __float_as_uint(ap[24]);
                a1[2] = __float_as_uint(ap[1072]);
                a1[3] = __float_as_uint(ap[1080]);

                MMA_OP(acc[0][0], a0, b0.x, b0.y);
                MMA_OP(acc[1][0], a1, b0.x, b0.y);
                MMA_OP(acc[0][1], a0, b0.z, b0.w);
                MMA_OP(acc[1][1], a1, b0.z, b0.w);
                MMA_OP(acc[0][2], a0, b1.x, b1.y);
                MMA_OP(acc[1][2], a1, b1.x, b1.y);
                MMA_OP(acc[0][3], a0, b1.z, b1.w);
                MMA_OP(acc[1][3], a1, b1.z, b1.w);
            }
        }
    }

    // ---- epilogue: direct store (full K accumulated per warp) ----
    const int co0 = coh * 32;
#pragma unroll
    for (int mt = 0; mt < 2; mt++) {
        const int pxm  = px0 + mt * 16 + (lane >> 2);
        const int h    = h0 + (pxm >> 6);
        const int wcol = w0 + (pxm & 63);
        float* o0 = out + (size_t)b * COUT_ * HW + (size_t)h * WW + wcol;
#pragma unroll
        for (int nt = 0; nt < 4; nt++) {
            const int co = co0 + nt * 8 + 2 * (lane & 3);
            float* p = o0 + (size_t)co * HW;
            p[0]      = acc[mt][nt][0];   // (px,    co)
            p[HW]     = acc[mt][nt][1];   // (px,    co+1)
            p[8]      = acc[mt][nt][2];   // (px+8,  co)
            p[HW + 8] = acc[mt][nt][3];   // (px+8,  co+1)
        }
    }
}

// ---------------------------------------------------------------------------
extern "C" void kernel_launch(void* const* d_in, const int* in_sizes, int n_in,
                              void* d_out, int out_size) {
    const float* X = (const float*)d_in[0];      // (16,64,256,256)
    const float* y = (const float*)d_in[1];      // (16,64)
    const float* w = (const float*)d_in[2];      // (64,64,3,3)
    float* out = (float*)d_out;                  // (16,64,256,256)

    float* wt;
    cudaGetSymbolAddress((void**)&wt, g_wt);

    cudaFuncSetAttribute(conv_mma_kernel,
                         cudaFuncAttributeMaxDynamicSharedMemorySize, DYN_SMEM);

    modw_kernel<<<dim3(COUT_, B_), CIN_>>>(w, y, wt);

    dim3 grid(WW / 64, HH / 2, B_);
    conv_mma_kernel<<<grid, 256, DYN_SMEM>>>(X, wt, out);
}

// round 10
// speedup vs baseline: 4.3063x; 4.3063x over previous
#include <cuda_runtime.h>
#include <cuda_fp16.h>
#include <cstdint>

#define B_    16
#define CIN_  64
#define COUT_ 64
#define HH    256
#define WW    256
#define HW    (HH * WW)
#define EPSF  1e-8f

// Demodulated fp16 weights in exact m16n8k16-B fragment-consumption order:
// [b][tap 0..8][kchunk 0..3][coh 0..1][sub 0..1][lane 0..31][4 x b32 words]
// word w (per lane l, n-tile j = sub*2 + (w>>1), reg = w&1):
//   half2{ B[k = 2*((l&3)) + reg*8][n = j*8 + (l>>2)],  B[k+1][n] }
// where k is ci within the 16-wide kchunk, B[k][n] = w1[co = coh*32 + n_glob][ci].
__device__ __align__(16) __half g_wt[B_ * 9 * 4 * 2 * 2 * 32 * 8];

#define MMA_F16(d, a, b0, b1)                                                 \
    asm volatile(                                                             \
        "mma.sync.aligned.m16n8k16.row.col.f32.f16.f16.f32 "                  \
        "{%0,%1,%2,%3},{%4,%5,%6,%7},{%8,%9},{%0,%1,%2,%3};"                  \
        : "+f"((d)[0]), "+f"((d)[1]), "+f"((d)[2]), "+f"((d)[3])              \
        : "r"((a)[0]), "r"((a)[1]), "r"((a)[2]), "r"((a)[3]),                 \
          "r"(b0), "r"(b1))

// ---------------------------------------------------------------------------
// Kernel 1: modulate + demodulate + fp16-round + swizzle into fragment order
// grid (COUT, B), block CIN.
// ---------------------------------------------------------------------------
__global__ void modw_kernel(const float* __restrict__ w,
                            const float* __restrict__ y,
                            __half* __restrict__ wt) {
    const int co = blockIdx.x;
    const int b  = blockIdx.y;
    const int ci = threadIdx.x;

    const float c  = 1.0f / 24.0f;               // (64*9)^-0.5
    const float yv = y[b * CIN_ + ci] * c;

    float v[9];
    float s = 0.0f;
    const float* wp = w + (co * CIN_ + ci) * 9;
#pragma unroll
    for (int t = 0; t < 9; t++) {
        v[t] = wp[t] * yv;
        s += v[t] * v[t];
    }
#pragma unroll
    for (int off = 16; off > 0; off >>= 1)
        s += __shfl_down_sync(0xffffffffu, s, off);
    __shared__ float ps[2];
    if ((ci & 31) == 0) ps[ci >> 5] = s;
    __syncthreads();
    const float d = rsqrtf(ps[0] + ps[1] + EPSF);

    const int kchunk = ci >> 4;
    const int k      = ci & 15;
    const int reg    = (k >> 3) & 1;
    const int lane   = (co & 7) * 4 + ((k & 7) >> 1);
    const int hsel   = k & 1;
    const int j      = (co >> 3) & 3;            // n-tile
    const int sub    = j >> 1;
    const int word   = (j & 1) * 2 + reg;
    const int coh    = co >> 5;

#pragma unroll
    for (int t = 0; t < 9; t++) {
        const size_t idx =
            (((((((size_t)(b * 9 + t) * 4 + kchunk) * 2 + coh) * 2 + sub)
               * 32 + lane) * 4 + word) * 2) + hsel;
        wt[idx] = __float2half_rn(v[t] * d);
    }
}

// ---------------------------------------------------------------------------
// Kernel 2: fp16 mma.sync (m16n8k16) implicit-GEMM conv, M32 x N32 warp tile.
// X staged ONCE as half2 pair-planes: xs32[pp 0..31][r 0..3][c 0..65],
//   pp = ci>>1, word = half2(ci_even, ci_odd); plane stride 264 (== 8 mod 32
//   -> the 4-plane x 8-col A LDS pattern hits all 32 banks, conflict-free).
// B loaded straight from gmem (fragment order, L1-resident LDG.128).
// 36 k16-steps, NO barriers in the mainloop. 3 CTAs/SM.
// CTA: 128 px (2h x 64w) x 64 co, 8 warps: (wid&3)->px group, (wid>>2)->co half.
// ---------------------------------------------------------------------------
#define XS_W32   (32 * 264)          // 8448 b32 words = 33.8 KB
#define DYN_SMEM (XS_W32 * 4)

__global__ void __launch_bounds__(256, 3)
conv_mma_kernel(const float* __restrict__ X,
                const __half* __restrict__ wt,
                float* __restrict__ out) {
    extern __shared__ __align__(16) uint32_t xs32[];
    __half* xs_h = (__half*)xs32;

    const int tid  = threadIdx.x;
    const int lane = tid & 31;
    const int wid  = tid >> 5;
    const int coh  = wid >> 2;           // co half (0/1)
    const int px0  = (wid & 3) * 32;     // warp pixel base

    const int b  = blockIdx.z;
    const int h0 = blockIdx.y * 2;
    const int w0 = blockIdx.x * 64;

    const float* Xb = X + (size_t)b * CIN_ * HW;
    // B fragment base for this warp (uint4 units): 4608 uint4 per sample
    const uint4* WbF = (const uint4*)(wt) + (size_t)b * 4608 + coh * 64 + lane;

    float acc[2][4][4];
#pragma unroll
    for (int mt = 0; mt < 2; mt++)
#pragma unroll
        for (int nt = 0; nt < 4; nt++)
#pragma unroll
            for (int q = 0; q < 4; q++) acc[mt][nt][q] = 0.0f;

    // ---- stage full X tile (64 ci planes) as fp16 pair-planes, div-free ----
    {
        int c = tid % 66, row = tid / 66, idx = tid;   // row = ci*4 + r
#pragma unroll
        for (int jj = 0; jj < 66; jj++) {
            const int ci = row >> 2;
            const int r  = row & 3;
            const int gh = h0 - 1 + r;
            const int gw = w0 - 1 + c;
            float v = 0.0f;
            if ((unsigned)gh < (unsigned)HH && (unsigned)gw < (unsigned)WW)
                v = Xb[(size_t)ci * HW + gh * WW + gw];
            xs_h[(size_t)((ci >> 1) * 264 + r * 66 + c) * 2 + (ci & 1)] =
                __float2half_rn(v);
            // advance 256 elements: 256 = 3*66 + 58
            idx += 256; c += 58; row += 3;
            if (c >= 66) { c -= 66; row += 1; }
            if (idx >= 64 * 4 * 66) break;
        }
    }
    __syncthreads();

    // per-warp A base (b32-word units)
    const int a_col  = (px0 & 63) + (lane >> 2);
    const int a_row0 = (px0 >> 6);

#pragma unroll
    for (int t = 0; t < 9; t++) {
        const int kh = t / 3, kw = t - kh * 3;
        const uint32_t* abase = xs32 + (size_t)(lane & 3) * 264
                              + (a_row0 + kh) * 66 + a_col + kw;

#pragma unroll
        for (int q = 0; q < 4; q++) {            // k16 chunk
            // B: 2 x LDG.128 (sub0: n-tiles 0,1 ; sub1: n-tiles 2,3)
            const uint4* bp = WbF + (size_t)(t * 4 + q) * 128;
            const uint4 bs0 = __ldg(bp);
            const uint4 bs1 = __ldg(bp + 32);

            // A: 8 LDS.32 (pair-planes q*8 + (lane&3) and +4)
            const uint32_t* ap = abase + (size_t)(q * 8) * 264;
            uint32_t a0[4], a1[4];
            a0[0] = ap[0];                // (r,    k pair)
            a0[1] = ap[8];                // (r+8,  k pair)
            a0[2] = ap[4 * 264];          // (r,    k+8 pair)
            a0[3] = ap[4 * 264 + 8];      // (r+8,  k+8 pair)
            a1[0] = ap[16];               // mt=1: rows +16
            a1[1] = ap[24];
            a1[2] = ap[4 * 264 + 16];
            a1[3] = ap[4 * 264 + 24];

            MMA_F16(acc[0][0], a0, bs0.x, bs0.y);
            MMA_F16(acc[1][0], a1, bs0.x, bs0.y);
            MMA_F16(acc[0][1], a0, bs0.z, bs0.w);
            MMA_F16(acc[1][1], a1, bs0.z, bs0.w);
            MMA_F16(acc[0][2], a0, bs1.x, bs1.y);
            MMA_F16(acc[1][2], a1, bs1.x, bs1.y);
            MMA_F16(acc[0][3], a0, bs1.z, bs1.w);
            MMA_F16(acc[1][3], a1, bs1.z, bs1.w);
        }
    }

    // ---- epilogue: direct store (full K accumulated per warp) ----
    const int co0 = coh * 32;
#pragma unroll
    for (int mt = 0; mt < 2; mt++) {
        const int pxm  = px0 + mt * 16 + (lane >> 2);
        const int h    = h0 + (pxm >> 6);
        const int wcol = w0 + (pxm & 63);
        float* o0 = out + (size_t)b * COUT_ * HW + (size_t)h * WW + wcol;
#pragma unroll
        for (int nt = 0; nt < 4; nt++) {
            const int co = co0 + nt * 8 + 2 * (lane & 3);
            float* p = o0 + (size_t)co * HW;
            p[0]      = acc[mt][nt][0];   // (px,    co)
            p[HW]     = acc[mt][nt][1];   // (px,    co+1)
            p[8]      = acc[mt][nt][2];   // (px+8,  co)
            p[HW + 8] = acc[mt][nt][3];   // (px+8,  co+1)
        }
    }
}

// ---------------------------------------------------------------------------
extern "C" void kernel_launch(void* const* d_in, const int* in_sizes, int n_in,
                              void* d_out, int out_size) {
    const float* X = (const float*)d_in[0];      // (16,64,256,256)
    const float* y = (const float*)d_in[1];      // (16,64)
    const float* w = (const float*)d_in[2];      // (64,64,3,3)
    float* out = (float*)d_out;                  // (16,64,256,256)

    __half* wt;
    cudaGetSymbolAddress((void**)&wt, g_wt);

    cudaFuncSetAttribute(conv_mma_kernel,
                         cudaFuncAttributeMaxDynamicSharedMemorySize, DYN_SMEM);

    modw_kernel<<<dim3(COUT_, B_), CIN_>>>(w, y, wt);

    dim3 grid(WW / 64, HH / 2, B_);
    conv_mma_kernel<<<grid, 256, DYN_SMEM>>>(X, wt, out);
}

// round 11
// speedup vs baseline: 4.4252x; 1.0276x over previous
#include <cuda_runtime.h>
#include <cuda_fp16.h>
#include <cstdint>

#define B_    16
#define CIN_  64
#define COUT_ 64
#define HH    256
#define WW    256
#define HW    (HH * WW)
#define EPSF  1e-8f

// Demodulated fp16 weights in exact m16n8k16-B fragment-consumption order:
// [b][tap 0..8][kchunk 0..3][coh 0..1][sub 0..1][lane 0..31][4 x b32 words]
__device__ __align__(16) __half g_wt[B_ * 9 * 4 * 2 * 2 * 32 * 8];

__device__ __forceinline__ uint32_t pack_h2(float lo, float hi) {
    uint32_t r;
    asm("cvt.rn.f16x2.f32 %0, %1, %2;" : "=r"(r) : "f"(hi), "f"(lo));
    return r;
}

#define MMA_F16(d, a, b0, b1)                                                 \
    asm volatile(                                                             \
        "mma.sync.aligned.m16n8k16.row.col.f32.f16.f16.f32 "                  \
        "{%0,%1,%2,%3},{%4,%5,%6,%7},{%8,%9},{%0,%1,%2,%3};"                  \
        : "+f"((d)[0]), "+f"((d)[1]), "+f"((d)[2]), "+f"((d)[3])              \
        : "r"((a)[0]), "r"((a)[1]), "r"((a)[2]), "r"((a)[3]),                 \
          "r"(b0), "r"(b1))

// ---------------------------------------------------------------------------
// Kernel 1: modulate + demodulate + fp16-round + swizzle into fragment order
// grid (COUT, B), block CIN.  (unchanged from R10 - validated)
// ---------------------------------------------------------------------------
__global__ void modw_kernel(const float* __restrict__ w,
                            const float* __restrict__ y,
                            __half* __restrict__ wt) {
    const int co = blockIdx.x;
    const int b  = blockIdx.y;
    const int ci = threadIdx.x;

    const float c  = 1.0f / 24.0f;               // (64*9)^-0.5
    const float yv = y[b * CIN_ + ci] * c;

    float v[9];
    float s = 0.0f;
    const float* wp = w + (co * CIN_ + ci) * 9;
#pragma unroll
    for (int t = 0; t < 9; t++) {
        v[t] = wp[t] * yv;
        s += v[t] * v[t];
    }
#pragma unroll
    for (int off = 16; off > 0; off >>= 1)
        s += __shfl_down_sync(0xffffffffu, s, off);
    __shared__ float ps[2];
    if ((ci & 31) == 0) ps[ci >> 5] = s;
    __syncthreads();
    const float d = rsqrtf(ps[0] + ps[1] + EPSF);

    const int kchunk = ci >> 4;
    const int k      = ci & 15;
    const int reg    = (k >> 3) & 1;
    const int lane   = (co & 7) * 4 + ((k & 7) >> 1);
    const int hsel   = k & 1;
    const int j      = (co >> 3) & 3;            // n-tile
    const int sub    = j >> 1;
    const int word   = (j & 1) * 2 + reg;
    const int coh    = co >> 5;

#pragma unroll
    for (int t = 0; t < 9; t++) {
        const size_t idx =
            (((((((size_t)(b * 9 + t) * 4 + kchunk) * 2 + coh) * 2 + sub)
               * 32 + lane) * 4 + word) * 2) + hsel;
        wt[idx] = __float2half_rn(v[t] * d);
    }
}

// ---------------------------------------------------------------------------
// Kernel 2: fp16 mma.sync (m16n8k16) implicit-GEMM conv, M32 x N32 warp tile.
// X staged ONCE as half2 pair-planes: xs32[pp 0..31][r 0..3][c 0..65],
//   pp = ci>>1 (plane stride 264 words -> conflict-free A LDS, proven R10).
// B loaded straight from gmem (fragment order, L1-resident LDG.128).
// kh/kw loops kept dynamic (unroll 1) so the 64-reg budget (4 CTAs/SM)
// holds without spills; q-block fully unrolled.
// ---------------------------------------------------------------------------
#define XS_W32   (32 * 264)          // 8448 b32 words = 33.8 KB
#define DYN_SMEM (XS_W32 * 4)

__global__ void __launch_bounds__(256, 4)
conv_mma_kernel(const float* __restrict__ X,
                const __half* __restrict__ wt,
                float* __restrict__ out) {
    extern __shared__ __align__(16) uint32_t xs32[];

    const int tid  = threadIdx.x;
    const int lane = tid & 31;
    const int wid  = tid >> 5;
    const int coh  = wid >> 2;           // co half (0/1)
    const int px0  = (wid & 3) * 32;     // warp pixel base

    const int b  = blockIdx.z;
    const int h0 = blockIdx.y * 2;
    const int w0 = blockIdx.x * 64;

    const float* Xb = X + (size_t)b * CIN_ * HW;
    const uint4* WbF = (const uint4*)(wt) + (size_t)b * 4608 + coh * 64 + lane;

    float acc[2][4][4];
#pragma unroll
    for (int mt = 0; mt < 2; mt++)
#pragma unroll
        for (int nt = 0; nt < 4; nt++)
#pragma unroll
            for (int q = 0; q < 4; q++) acc[mt][nt][q] = 0.0f;

    // ---- stage full X tile as fp16 pair-planes (packed cvt, STS.32) ----
    {
        const int pp = tid >> 3;          // pair-plane 0..31
        const int l8 = tid & 7;
        const float* x0 = Xb + (size_t)(2 * pp) * HW;
        uint32_t* dst = xs32 + pp * 264;
#pragma unroll
        for (int r = 0; r < 4; r++) {
            const int gh = h0 - 1 + r;
            const bool hok = (unsigned)gh < (unsigned)HH;
            const float* xr = x0 + gh * WW;
#pragma unroll
            for (int cb = 0; cb < 9; cb++) {
                const int c  = cb * 8 + l8;
                const int gw = w0 - 1 + c;
                float v0 = 0.0f, v1 = 0.0f;
                if ((c < 66) & hok & ((unsigned)gw < (unsigned)WW)) {
                    v0 = __ldg(xr + gw);
                    v1 = __ldg(xr + HW + gw);
                }
                if (c < 66)
                    dst[r * 66 + c] = pack_h2(v0, v1);
            }
        }
    }
    __syncthreads();

    // per-warp A base (b32-word units)
    const uint32_t* xwarp = xs32 + (size_t)(lane & 3) * 264
                          + (px0 >> 6) * 66 + (px0 & 63) + (lane >> 2);
    const uint4* bp = WbF;               // rolls forward 128 uint4 per q-step

#pragma unroll 1
    for (int kh = 0; kh < 3; kh++) {
#pragma unroll 1
        for (int kw = 0; kw < 3; kw++) {
            const uint32_t* abase = xwarp + kh * 66 + kw;

#pragma unroll
            for (int q = 0; q < 4; q++) {        // k16 chunk
                const uint4 bs0 = __ldg(bp);          // n-tiles 0,1
                const uint4 bs1 = __ldg(bp + 32);     // n-tiles 2,3

                const uint32_t* ap = abase + (size_t)(q * 8) * 264;
                uint32_t a0[4], a1[4];
                a0[0] = ap[0];
                a0[1] = ap[8];
                a0[2] = ap[4 * 264];
                a0[3] = ap[4 * 264 + 8];
                a1[0] = ap[16];
                a1[1] = ap[24];
                a1[2] = ap[4 * 264 + 16];
                a1[3] = ap[4 * 264 + 24];

                MMA_F16(acc[0][0], a0, bs0.x, bs0.y);
                MMA_F16(acc[1][0], a1, bs0.x, bs0.y);
                MMA_F16(acc[0][1], a0, bs0.z, bs0.w);
                MMA_F16(acc[1][1], a1, bs0.z, bs0.w);
                MMA_F16(acc[0][2], a0, bs1.x, bs1.y);
                MMA_F16(acc[1][2], a1, bs1.x, bs1.y);
                MMA_F16(acc[0][3], a0, bs1.z, bs1.w);
                MMA_F16(acc[1][3], a1, bs1.z, bs1.w);

                bp += 128;
            }
        }
    }

    // ---- epilogue: direct store (full K accumulated per warp) ----
    const int co0 = coh * 32;
#pragma unroll
    for (int mt = 0; mt < 2; mt++) {
        const int pxm  = px0 + mt * 16 + (lane >> 2);
        const int h    = h0 + (pxm >> 6);
        const int wcol = w0 + (pxm & 63);
        float* o0 = out + (size_t)b * COUT_ * HW + (size_t)h * WW + wcol;
#pragma unroll
        for (int nt = 0; nt < 4; nt++) {
            const int co = co0 + nt * 8 + 2 * (lane & 3);
            float* p = o0 + (size_t)co * HW;
            p[0]      = acc[mt][nt][0];   // (px,    co)
            p[HW]     = acc[mt][nt][1];   // (px,    co+1)
            p[8]      = acc[mt][nt][2];   // (px+8,  co)
            p[HW + 8] = acc[mt][nt][3];   // (px+8,  co+1)
        }
    }
}

// ---------------------------------------------------------------------------
extern "C" void kernel_launch(void* const* d_in, const int* in_sizes, int n_in,
                              void* d_out, int out_size) {
    const float* X = (const float*)d_in[0];      // (16,64,256,256)
    const float* y = (const float*)d_in[1];      // (16,64)
    const float* w = (const float*)d_in[2];      // (64,64,3,3)
    float* out = (float*)d_out;                  // (16,64,256,256)

    __half* wt;
    cudaGetSymbolAddress((void**)&wt, g_wt);

    cudaFuncSetAttribute(conv_mma_kernel,
                         cudaFuncAttributeMaxDynamicSharedMemorySize, DYN_SMEM);

    modw_kernel<<<dim3(COUT_, B_), CIN_>>>(w, y, wt);

    dim3 grid(WW / 64, HH / 2, B_);
    conv_mma_kernel<<<grid, 256, DYN_SMEM>>>(X, wt, out);
}